// round 13
// baseline (speedup 1.0000x reference)
#include <cuda_runtime.h>
#include <cuda_fp16.h>
#include <cstdint>

#define BATCH 4096
#define IN_C 1024
#define OUT_C 1024
#define KDIM 8192   // IN_C * 8

// Scratch (static device globals — allocation-free per harness rules)
static __device__ __align__(1024) __half g_basis[(size_t)BATCH * KDIM]; // 64 MB
static __device__ __align__(1024) __half g_coef[(size_t)OUT_C * KDIM];  // 16 MB

__device__ __forceinline__ uint32_t smem_u32(const void* p) {
    uint32_t a;
    asm("{ .reg .u64 t; cvta.to.shared.u64 t, %1; cvt.u32.u64 %0, t; }"
        : "=r"(a) : "l"(p));
    return a;
}
__device__ __forceinline__ float tanhap(float z) {
    float r;
    asm("tanh.approx.f32 %0, %1;" : "=f"(r) : "f"(z));
    return r;
}

// ---------------------------------------------------------------------------
// Kernel 1: basis[b, i*8+m] = 0.5 + 0.5*tanh(s*(u - c_m)),  u = alpha*x + beta
// One MUFU (tanh.approx) per output value.
// ---------------------------------------------------------------------------
__global__ void k_basis(const float* __restrict__ x, const float* __restrict__ centers,
                        const float* __restrict__ slopes, const float* __restrict__ alpha,
                        const float* __restrict__ beta) {
    int idx = blockIdx.x * blockDim.x + threadIdx.x;  // b * IN_C + i
    int i = idx & (IN_C - 1);
    float u = fmaf(alpha[i], x[idx], beta[i]);
    float s = slopes[8 * i];
    float4 c0 = reinterpret_cast<const float4*>(centers)[2 * i];
    float4 c1 = reinterpret_cast<const float4*>(centers)[2 * i + 1];
    float cc[8] = {c0.x, c0.y, c0.z, c0.w, c1.x, c1.y, c1.z, c1.w};
    union { __half h[8]; uint4 v; } out;
#pragma unroll
    for (int m = 0; m < 8; m++) {
        float t = tanhap(s * (u - cc[m]));
        out.h[m] = __float2half_rn(fmaf(t, 0.5f, 0.5f));
    }
    reinterpret_cast<uint4*>(g_basis)[idx] = out.v;
}

// ---------------------------------------------------------------------------
// Kernel 2: coeffs fp32 -> fp16 (layout [o, i*8+m] is already K-major)
// ---------------------------------------------------------------------------
__global__ void k_conv(const float* __restrict__ c) {
    int idx = blockIdx.x * blockDim.x + threadIdx.x;  // per 4 floats
    float4 v = reinterpret_cast<const float4*>(c)[idx];
    union { __half2 h2[2]; uint2 u; } o;
    o.h2[0] = __floats2half2_rn(v.x, v.y);
    o.h2[1] = __floats2half2_rn(v.z, v.w);
    reinterpret_cast<uint2*>(g_coef)[idx] = o.u;
}

// ---------------------------------------------------------------------------
// Kernel 3: HMMA fp16 GEMM  y[4096,1024] = basis @ coef^T
// mma.sync m16n8k16, BM=128, BN=128, BK=64, 64x64 warp tiles (4 warps),
// 3-stage cp.async pipeline, 2 CTAs/SM (96KB smem each) so per-chunk barrier
// bubbles of one CTA are covered by the other CTA's MMAs.
// Grid 8x32 = 256 CTAs = one wave at 2 CTA/SM.
// ---------------------------------------------------------------------------
#define BM 128
#define BN 128
#define BK 64
#define STAGES 3
#define NTHR 128
#define NCHUNK (KDIM / BK)          // 128

#define A_BYTES (BM * 128)          // 16 KB  (128B row = 64 fp16 = BK)
#define B_BYTES (BN * 128)          // 16 KB
#define STG_BYTES (A_BYTES + B_BYTES)      // 32 KB
#define SM_TOTAL (STAGES * STG_BYTES)      // 96 KB

__device__ __forceinline__ void cp16(uint32_t dst, const void* src) {
    asm volatile("cp.async.cg.shared.global [%0], [%1], 16;" :: "r"(dst), "l"(src));
}
__device__ __forceinline__ void ldm_x4(uint32_t& r0, uint32_t& r1, uint32_t& r2, uint32_t& r3, uint32_t addr) {
    asm volatile("ldmatrix.sync.aligned.m8n8.x4.shared.b16 {%0,%1,%2,%3}, [%4];"
                 : "=r"(r0), "=r"(r1), "=r"(r2), "=r"(r3) : "r"(addr));
}
__device__ __forceinline__ void mma16816(float* d, const uint32_t* a, const uint32_t* b) {
    asm volatile("mma.sync.aligned.m16n8k16.row.col.f32.f16.f16.f32 "
                 "{%0,%1,%2,%3}, {%4,%5,%6,%7}, {%8,%9}, {%0,%1,%2,%3};"
                 : "+f"(d[0]), "+f"(d[1]), "+f"(d[2]), "+f"(d[3])
                 : "r"(a[0]), "r"(a[1]), "r"(a[2]), "r"(a[3]), "r"(b[0]), "r"(b[1]));
}

// Smem tile layout: row r x 128 bytes; physical = r*128 + (c16*16 ^ ((r&7)<<4))
__device__ __forceinline__ void load_stage(uint32_t sb, int stage,
                                           const __half* Ag, const __half* Bg,
                                           int chunk, int tid) {
    uint32_t sA = sb + stage * STG_BYTES;
    uint32_t sB = sA + A_BYTES;
    const char* gA = (const char*)Ag + (size_t)chunk * (BK * 2);
    const char* gB = (const char*)Bg + (size_t)chunk * (BK * 2);
#pragma unroll
    for (int j = 0; j < (A_BYTES / 16) / NTHR; j++) {   // 8 iters
        int seg = tid + j * NTHR;                       // row = seg>>3, c16 = seg&7
        uint32_t row = (uint32_t)seg >> 3;
        uint32_t off = row * 128u + ((((uint32_t)seg & 7u) * 16u) ^ ((row & 7u) << 4));
        size_t gofs = (size_t)row * (KDIM * 2) + (size_t)((seg & 7) << 4);
        cp16(sA + off, gA + gofs);
        cp16(sB + off, gB + gofs);
    }
}

__global__ void __launch_bounds__(NTHR, 2)
k_gemm(float* __restrict__ y) {
    extern __shared__ char smem[];
    uint32_t sb = smem_u32(smem);
    int tid = threadIdx.x;
    int wid = tid >> 5, lid = tid & 31;
    int tn = blockIdx.x, tm = blockIdx.y;
    const __half* Ag = g_basis + (size_t)tm * BM * KDIM;
    const __half* Bg = g_coef + (size_t)tn * BN * KDIM;

    int wm = wid >> 1;          // 0..1 -> warp rows wm*64
    int wn = wid & 1;           // 0..1 -> warp cols wn*64

    // A fragments: mt 0..3 (m16 each)
    uint32_t aRow[4], aXor[4];
#pragma unroll
    for (int mt = 0; mt < 4; mt++) {
        aRow[mt] = (uint32_t)(wm * 64 + mt * 16 + (lid & 15));
        aXor[mt] = (aRow[mt] & 7u) << 4;
    }
    uint32_t aCol = (uint32_t)((lid >> 4) * 16);

    // B fragments: p 0..3 (n16 each -> two n8 tiles)
    uint32_t bRow[4], bXor[4];
#pragma unroll
    for (int p = 0; p < 4; p++) {
        bRow[p] = (uint32_t)(wn * 64 + p * 16 + ((lid >> 4) << 3) + (lid & 7));
        bXor[p] = (bRow[p] & 7u) << 4;
    }
    uint32_t bCol = (uint32_t)(((lid >> 3) & 1) * 16);

    float acc[4][8][4];
#pragma unroll
    for (int mt = 0; mt < 4; mt++)
#pragma unroll
        for (int nt = 0; nt < 8; nt++)
#pragma unroll
            for (int q = 0; q < 4; q++) acc[mt][nt][q] = 0.0f;

    // Prologue: stages 0..STAGES-2
#pragma unroll
    for (int s = 0; s < STAGES - 1; s++) {
        load_stage(sb, s, Ag, Bg, s, tid);
        asm volatile("cp.async.commit_group;" ::: "memory");
    }

    uint32_t afr[2][4][4];   // [buf][mt][4]
    uint32_t bfr[2][4][4];   // [buf][p][4]

#pragma unroll 1
    for (int c = 0; c < NCHUNK; c++) {
        asm volatile("cp.async.wait_group %0;" :: "n"(STAGES - 2) : "memory");
        __syncthreads();
        // Refill stage used by chunk c-1 (all warps finished it before this barrier)
        int nc = c + STAGES - 1;
        if (nc < NCHUNK) load_stage(sb, nc % STAGES, Ag, Bg, nc, tid);
        asm volatile("cp.async.commit_group;" ::: "memory");

        uint32_t sA = sb + (uint32_t)(c % STAGES) * STG_BYTES;
        uint32_t sB = sA + A_BYTES;

        // kk = 0 fragments into buf 0
#pragma unroll
        for (int mt = 0; mt < 4; mt++)
            ldm_x4(afr[0][mt][0], afr[0][mt][1], afr[0][mt][2], afr[0][mt][3],
                   sA + aRow[mt] * 128u + (aCol ^ aXor[mt]));
#pragma unroll
        for (int p = 0; p < 4; p++)
            ldm_x4(bfr[0][p][0], bfr[0][p][1], bfr[0][p][2], bfr[0][p][3],
                   sB + bRow[p] * 128u + (bCol ^ bXor[p]));

#pragma unroll
        for (int kk = 0; kk < 4; kk++) {
            int cur = kk & 1, nxt = cur ^ 1;
            if (kk < 3) {
                uint32_t koff = (uint32_t)(kk + 1) * 32u;
#pragma unroll
                for (int mt = 0; mt < 4; mt++)
                    ldm_x4(afr[nxt][mt][0], afr[nxt][mt][1], afr[nxt][mt][2], afr[nxt][mt][3],
                           sA + aRow[mt] * 128u + ((koff + aCol) ^ aXor[mt]));
#pragma unroll
                for (int p = 0; p < 4; p++)
                    ldm_x4(bfr[nxt][p][0], bfr[nxt][p][1], bfr[nxt][p][2], bfr[nxt][p][3],
                           sB + bRow[p] * 128u + ((koff + bCol) ^ bXor[p]));
            }
#pragma unroll
            for (int mt = 0; mt < 4; mt++)
#pragma unroll
                for (int p = 0; p < 4; p++) {
                    mma16816(acc[mt][2 * p + 0], afr[cur][mt], &bfr[cur][p][0]);
                    mma16816(acc[mt][2 * p + 1], afr[cur][mt], &bfr[cur][p][2]);
                }
        }
    }
    asm volatile("cp.async.wait_group 0;" ::: "memory");

    // Epilogue: direct float2 stores
    int r0 = wm * 64 + (lid >> 2);
    int cb = wn * 64 + (lid & 3) * 2;
#pragma unroll
    for (int mt = 0; mt < 4; mt++) {
#pragma unroll
        for (int nt = 0; nt < 8; nt++) {
            int row = tm * BM + r0 + mt * 16;
            int col = tn * BN + cb + nt * 8;
            float2 v0 = make_float2(acc[mt][nt][0], acc[mt][nt][1]);
            float2 v1 = make_float2(acc[mt][nt][2], acc[mt][nt][3]);
            *reinterpret_cast<float2*>(y + (size_t)row * OUT_C + col) = v0;
            *reinterpret_cast<float2*>(y + (size_t)(row + 8) * OUT_C + col) = v1;
        }
    }
}

// ---------------------------------------------------------------------------
extern "C" void kernel_launch(void* const* d_in, const int* in_sizes, int n_in,
                              void* d_out, int out_size) {
    (void)in_sizes; (void)n_in; (void)out_size;
    const float* x       = (const float*)d_in[0];
    const float* coeffs  = (const float*)d_in[1];
    const float* centers = (const float*)d_in[2];
    const float* slopes  = (const float*)d_in[3];
    const float* alpha   = (const float*)d_in[4];
    const float* beta    = (const float*)d_in[5];
    float* y = (float*)d_out;

    k_basis<<<(BATCH * IN_C) / 256, 256>>>(x, centers, slopes, alpha, beta);
    k_conv<<<(OUT_C * KDIM / 4) / 256, 256>>>(coeffs);
    cudaFuncSetAttribute(k_gemm, cudaFuncAttributeMaxDynamicSharedMemorySize, SM_TOTAL);
    k_gemm<<<dim3(OUT_C / BN, BATCH / BM), NTHR, SM_TOTAL>>>(y);
}

// round 14
// speedup vs baseline: 1.0696x; 1.0696x over previous
#include <cuda_runtime.h>
#include <cuda_fp16.h>
#include <cstdint>

#define BATCH 4096
#define IN_C 1024
#define OUT_C 1024
#define KDIM 8192   // IN_C * 8

// Scratch (static device globals — allocation-free per harness rules)
static __device__ __align__(1024) __half g_basis[(size_t)BATCH * KDIM]; // 64 MB
static __device__ __align__(1024) __half g_coef[(size_t)OUT_C * KDIM];  // 16 MB

__device__ __forceinline__ uint32_t smem_u32(const void* p) {
    uint32_t a;
    asm("{ .reg .u64 t; cvta.to.shared.u64 t, %1; cvt.u32.u64 %0, t; }"
        : "=r"(a) : "l"(p));
    return a;
}
__device__ __forceinline__ float tanhap(float z) {
    float r;
    asm("tanh.approx.f32 %0, %1;" : "=f"(r) : "f"(z));
    return r;
}

// ---------------------------------------------------------------------------
// Fused pre-kernel.
//   Blocks [0, NB_BASIS): basis[b, i*8+m] = 0.5 + 0.5*tanh(s*(u - c_m)),
//     each thread computes TWO batch rows (b and b+2048) sharing i-parameters.
//   Blocks [NB_BASIS, NB_BASIS+NB_CONV): coeffs fp32 -> fp16 copy.
// ---------------------------------------------------------------------------
#define NB_BASIS ((BATCH / 2) * IN_C / 256)     // 8192
#define NB_CONV  ((OUT_C * KDIM / 4) / 256)     // 8192
#define HALF_OFF ((size_t)(BATCH / 2) * IN_C)   // element offset for b+2048

__global__ void k_pre(const float* __restrict__ x, const float* __restrict__ coeffs,
                      const float* __restrict__ centers, const float* __restrict__ slopes,
                      const float* __restrict__ alpha, const float* __restrict__ beta) {
    int blk = blockIdx.x;
    if (blk < NB_BASIS) {
        int t = blk * 256 + threadIdx.x;       // 0 .. 2M-1 ; b1 = t>>10, i = t&1023
        int i = t & (IN_C - 1);
        float a = alpha[i], be = beta[i];
        float s = slopes[8 * i];
        float4 c0 = reinterpret_cast<const float4*>(centers)[2 * i];
        float4 c1 = reinterpret_cast<const float4*>(centers)[2 * i + 1];
        float cc[8] = {c0.x, c0.y, c0.z, c0.w, c1.x, c1.y, c1.z, c1.w};
        float u0 = fmaf(a, x[t], be);
        float u1 = fmaf(a, x[t + HALF_OFF], be);
        union { __half h[8]; uint4 v; } o0, o1;
#pragma unroll
        for (int m = 0; m < 8; m++) {
            float t0 = tanhap(s * (u0 - cc[m]));
            float t1 = tanhap(s * (u1 - cc[m]));
            o0.h[m] = __float2half_rn(fmaf(t0, 0.5f, 0.5f));
            o1.h[m] = __float2half_rn(fmaf(t1, 0.5f, 0.5f));
        }
        reinterpret_cast<uint4*>(g_basis)[t] = o0.v;
        reinterpret_cast<uint4*>(g_basis)[t + HALF_OFF] = o1.v;
    } else {
        int idx = (blk - NB_BASIS) * 256 + threadIdx.x;  // per 4 floats
        float4 v = reinterpret_cast<const float4*>(coeffs)[idx];
        union { __half2 h2[2]; uint2 u; } o;
        o.h2[0] = __floats2half2_rn(v.x, v.y);
        o.h2[1] = __floats2half2_rn(v.z, v.w);
        reinterpret_cast<uint2*>(g_coef)[idx] = o.u;
    }
}

// ---------------------------------------------------------------------------
// HMMA fp16 GEMM  y[4096,1024] = basis @ coef^T       (unchanged from best)
// mma.sync m16n8k16, BM=128, BN=256, BK=64, 64x64 warp tiles (8 warps),
// 4-stage cp.async pipeline, XOR-swizzled smem + ldmatrix.x4,
// fragment double-buffering across k-steps. Grid 4x32 = 128 CTAs, one wave.
// ---------------------------------------------------------------------------
#define BM 128
#define BN 256
#define BK 64
#define STAGES 4
#define NTHR 256
#define NCHUNK (KDIM / BK)          // 128

#define A_BYTES (BM * 128)          // 16 KB  (128B row = 64 fp16 = BK)
#define B_BYTES (BN * 128)          // 32 KB
#define STG_BYTES (A_BYTES + B_BYTES)      // 48 KB
#define SM_TOTAL (STAGES * STG_BYTES)      // 192 KB

__device__ __forceinline__ void cp16(uint32_t dst, const void* src) {
    asm volatile("cp.async.cg.shared.global [%0], [%1], 16;" :: "r"(dst), "l"(src));
}
__device__ __forceinline__ void ldm_x4(uint32_t& r0, uint32_t& r1, uint32_t& r2, uint32_t& r3, uint32_t addr) {
    asm volatile("ldmatrix.sync.aligned.m8n8.x4.shared.b16 {%0,%1,%2,%3}, [%4];"
                 : "=r"(r0), "=r"(r1), "=r"(r2), "=r"(r3) : "r"(addr));
}
__device__ __forceinline__ void mma16816(float* d, const uint32_t* a, const uint32_t* b) {
    asm volatile("mma.sync.aligned.m16n8k16.row.col.f32.f16.f16.f32 "
                 "{%0,%1,%2,%3}, {%4,%5,%6,%7}, {%8,%9}, {%0,%1,%2,%3};"
                 : "+f"(d[0]), "+f"(d[1]), "+f"(d[2]), "+f"(d[3])
                 : "r"(a[0]), "r"(a[1]), "r"(a[2]), "r"(a[3]), "r"(b[0]), "r"(b[1]));
}

// Smem tile layout: row r x 128 bytes; physical = r*128 + (c16*16 ^ ((r&7)<<4))
__device__ __forceinline__ void load_stage(uint32_t sb, int stage,
                                           const __half* Ag, const __half* Bg,
                                           int chunk, int tid) {
    uint32_t sA = sb + stage * STG_BYTES;
    uint32_t sB = sA + A_BYTES;
    const char* gA = (const char*)Ag + (size_t)chunk * (BK * 2);
    const char* gB = (const char*)Bg + (size_t)chunk * (BK * 2);
#pragma unroll
    for (int j = 0; j < (A_BYTES / 16) / NTHR; j++) {   // 4 iters
        int seg = tid + j * NTHR;                       // row = seg>>3, c16 = seg&7
        uint32_t row = (uint32_t)seg >> 3;
        uint32_t off = row * 128u + ((((uint32_t)seg & 7u) * 16u) ^ ((row & 7u) << 4));
        cp16(sA + off, gA + (size_t)row * (KDIM * 2) + (size_t)((seg & 7) << 4));
    }
#pragma unroll
    for (int j = 0; j < (B_BYTES / 16) / NTHR; j++) {   // 8 iters
        int seg = tid + j * NTHR;
        uint32_t row = (uint32_t)seg >> 3;
        uint32_t off = row * 128u + ((((uint32_t)seg & 7u) * 16u) ^ ((row & 7u) << 4));
        cp16(sB + off, gB + (size_t)row * (KDIM * 2) + (size_t)((seg & 7) << 4));
    }
}

__global__ void __launch_bounds__(NTHR, 1)
k_gemm(float* __restrict__ y) {
    extern __shared__ char smem[];
    uint32_t sb = smem_u32(smem);
    int tid = threadIdx.x;
    int wid = tid >> 5, lid = tid & 31;
    int tn = blockIdx.x, tm = blockIdx.y;
    const __half* Ag = g_basis + (size_t)tm * BM * KDIM;
    const __half* Bg = g_coef + (size_t)tn * BN * KDIM;

    int wm = wid >> 2;          // 0..1 -> warp rows wm*64
    int wn = wid & 3;           // 0..3 -> warp cols wn*64

    // A fragments: mt 0..3 (m16 each)
    uint32_t aRow[4], aXor[4];
#pragma unroll
    for (int mt = 0; mt < 4; mt++) {
        aRow[mt] = (uint32_t)(wm * 64 + mt * 16 + (lid & 15));
        aXor[mt] = (aRow[mt] & 7u) << 4;
    }
    uint32_t aCol = (uint32_t)((lid >> 4) * 16);

    // B fragments: p 0..3 (n16 each -> two n8 tiles)
    uint32_t bRow[4], bXor[4];
#pragma unroll
    for (int p = 0; p < 4; p++) {
        bRow[p] = (uint32_t)(wn * 64 + p * 16 + ((lid >> 4) << 3) + (lid & 7));
        bXor[p] = (bRow[p] & 7u) << 4;
    }
    uint32_t bCol = (uint32_t)(((lid >> 3) & 1) * 16);

    float acc[4][8][4];
#pragma unroll
    for (int mt = 0; mt < 4; mt++)
#pragma unroll
        for (int nt = 0; nt < 8; nt++)
#pragma unroll
            for (int q = 0; q < 4; q++) acc[mt][nt][q] = 0.0f;

    // Prologue: stages 0..STAGES-2
#pragma unroll
    for (int s = 0; s < STAGES - 1; s++) {
        load_stage(sb, s, Ag, Bg, s, tid);
        asm volatile("cp.async.commit_group;" ::: "memory");
    }

    uint32_t afr[2][4][4];   // [buf][mt][4]
    uint32_t bfr[2][4][4];   // [buf][p][4]

#pragma unroll 1
    for (int c = 0; c < NCHUNK; c++) {
        asm volatile("cp.async.wait_group %0;" :: "n"(STAGES - 2) : "memory");
        __syncthreads();
        // Refill stage used by chunk c-1 (all warps finished it before this barrier)
        int nc = c + STAGES - 1;
        if (nc < NCHUNK) load_stage(sb, nc % STAGES, Ag, Bg, nc, tid);
        asm volatile("cp.async.commit_group;" ::: "memory");

        uint32_t sA = sb + (uint32_t)(c % STAGES) * STG_BYTES;
        uint32_t sB = sA + A_BYTES;

        // kk = 0 fragments into buf 0
#pragma unroll
        for (int mt = 0; mt < 4; mt++)
            ldm_x4(afr[0][mt][0], afr[0][mt][1], afr[0][mt][2], afr[0][mt][3],
                   sA + aRow[mt] * 128u + (aCol ^ aXor[mt]));
#pragma unroll
        for (int p = 0; p < 4; p++)
            ldm_x4(bfr[0][p][0], bfr[0][p][1], bfr[0][p][2], bfr[0][p][3],
                   sB + bRow[p] * 128u + (bCol ^ bXor[p]));

#pragma unroll
        for (int kk = 0; kk < 4; kk++) {
            int cur = kk & 1, nxt = cur ^ 1;
            if (kk < 3) {
                uint32_t koff = (uint32_t)(kk + 1) * 32u;
#pragma unroll
                for (int mt = 0; mt < 4; mt++)
                    ldm_x4(afr[nxt][mt][0], afr[nxt][mt][1], afr[nxt][mt][2], afr[nxt][mt][3],
                           sA + aRow[mt] * 128u + ((koff + aCol) ^ aXor[mt]));
#pragma unroll
                for (int p = 0; p < 4; p++)
                    ldm_x4(bfr[nxt][p][0], bfr[nxt][p][1], bfr[nxt][p][2], bfr[nxt][p][3],
                           sB + bRow[p] * 128u + ((koff + bCol) ^ bXor[p]));
            }
#pragma unroll
            for (int mt = 0; mt < 4; mt++)
#pragma unroll
                for (int p = 0; p < 4; p++) {
                    mma16816(acc[mt][2 * p + 0], afr[cur][mt], &bfr[cur][p][0]);
                    mma16816(acc[mt][2 * p + 1], afr[cur][mt], &bfr[cur][p][2]);
                }
        }
    }
    asm volatile("cp.async.wait_group 0;" ::: "memory");

    // Epilogue: direct float2 stores
    int r0 = wm * 64 + (lid >> 2);
    int cb = wn * 64 + (lid & 3) * 2;
#pragma unroll
    for (int mt = 0; mt < 4; mt++) {
#pragma unroll
        for (int nt = 0; nt < 8; nt++) {
            int row = tm * BM + r0 + mt * 16;
            int col = tn * BN + cb + nt * 8;
            float2 v0 = make_float2(acc[mt][nt][0], acc[mt][nt][1]);
            float2 v1 = make_float2(acc[mt][nt][2], acc[mt][nt][3]);
            *reinterpret_cast<float2*>(y + (size_t)row * OUT_C + col) = v0;
            *reinterpret_cast<float2*>(y + (size_t)(row + 8) * OUT_C + col) = v1;
        }
    }
}

// ---------------------------------------------------------------------------
extern "C" void kernel_launch(void* const* d_in, const int* in_sizes, int n_in,
                              void* d_out, int out_size) {
    (void)in_sizes; (void)n_in; (void)out_size;
    const float* x       = (const float*)d_in[0];
    const float* coeffs  = (const float*)d_in[1];
    const float* centers = (const float*)d_in[2];
    const float* slopes  = (const float*)d_in[3];
    const float* alpha   = (const float*)d_in[4];
    const float* beta    = (const float*)d_in[5];
    float* y = (float*)d_out;

    k_pre<<<NB_BASIS + NB_CONV, 256>>>(x, coeffs, centers, slopes, alpha, beta);
    cudaFuncSetAttribute(k_gemm, cudaFuncAttributeMaxDynamicSharedMemorySize, SM_TOTAL);
    k_gemm<<<dim3(OUT_C / BN, BATCH / BM), NTHR, SM_TOTAL>>>(y);
}

// round 16
// speedup vs baseline: 1.1110x; 1.0387x over previous
#include <cuda_runtime.h>
#include <cuda_fp16.h>
#include <cstdint>

#define BATCH 4096
#define IN_C 1024
#define OUT_C 1024
#define KDIM 8192   // IN_C * 8

// Scratch (static device globals — allocation-free per harness rules)
static __device__ __align__(1024) __half g_basis[(size_t)BATCH * KDIM]; // 64 MB
static __device__ __align__(1024) __half g_coef[(size_t)OUT_C * KDIM];  // 16 MB

__device__ __forceinline__ uint32_t smem_u32(const void* p) {
    uint32_t a;
    asm("{ .reg .u64 t; cvta.to.shared.u64 t, %1; cvt.u32.u64 %0, t; }"
        : "=r"(a) : "l"(p));
    return a;
}
__device__ __forceinline__ float tanhap(float z) {
    float r;
    asm("tanh.approx.f32 %0, %1;" : "=f"(r) : "f"(z));
    return r;
}

// ---------------------------------------------------------------------------
// Fused pre-kernel (unchanged from best).
// ---------------------------------------------------------------------------
#define NB_BASIS ((BATCH / 2) * IN_C / 256)     // 8192
#define NB_CONV  ((OUT_C * KDIM / 4) / 256)     // 8192
#define HALF_OFF ((size_t)(BATCH / 2) * IN_C)   // element offset for b+2048

__global__ void k_pre(const float* __restrict__ x, const float* __restrict__ coeffs,
                      const float* __restrict__ centers, const float* __restrict__ slopes,
                      const float* __restrict__ alpha, const float* __restrict__ beta) {
    int blk = blockIdx.x;
    if (blk < NB_BASIS) {
        int t = blk * 256 + threadIdx.x;       // 0 .. 2M-1 ; i = t&1023
        int i = t & (IN_C - 1);
        float a = alpha[i], be = beta[i];
        float s = slopes[8 * i];
        float4 c0 = reinterpret_cast<const float4*>(centers)[2 * i];
        float4 c1 = reinterpret_cast<const float4*>(centers)[2 * i + 1];
        float cc[8] = {c0.x, c0.y, c0.z, c0.w, c1.x, c1.y, c1.z, c1.w};
        float u0 = fmaf(a, x[t], be);
        float u1 = fmaf(a, x[t + HALF_OFF], be);
        union { __half h[8]; uint4 v; } o0, o1;
#pragma unroll
        for (int m = 0; m < 8; m++) {
            float t0 = tanhap(s * (u0 - cc[m]));
            float t1 = tanhap(s * (u1 - cc[m]));
            o0.h[m] = __float2half_rn(fmaf(t0, 0.5f, 0.5f));
            o1.h[m] = __float2half_rn(fmaf(t1, 0.5f, 0.5f));
        }
        reinterpret_cast<uint4*>(g_basis)[t] = o0.v;
        reinterpret_cast<uint4*>(g_basis)[t + HALF_OFF] = o1.v;
    } else {
        int idx = (blk - NB_BASIS) * 256 + threadIdx.x;  // per 4 floats
        float4 v = reinterpret_cast<const float4*>(coeffs)[idx];
        union { __half2 h2[2]; uint2 u; } o;
        o.h2[0] = __floats2half2_rn(v.x, v.y);
        o.h2[1] = __floats2half2_rn(v.z, v.w);
        reinterpret_cast<uint2*>(g_coef)[idx] = o.u;
    }
}

// ---------------------------------------------------------------------------
// HMMA fp16 GEMM  y[4096,1024] = basis @ coef^T
// mma.sync m16n8k16, BM=128, BN=256, BK=64, 64x64 warp tiles (8 warps),
// 4 stages processed as PAIRS: one __syncthreads + one refill (2 chunks) per
// 128 K, 8 uninterrupted k-steps between barriers.
// Grid 4x32 = 128 CTAs = one wave.
// ---------------------------------------------------------------------------
#define BM 128
#define BN 256
#define BK 64
#define NTHR 256
#define NCHUNK (KDIM / BK)          // 128
#define NPAIR (NCHUNK / 2)          // 64

#define A_BYTES (BM * 128)          // 16 KB  (128B row = 64 fp16 = BK)
#define B_BYTES (BN * 128)          // 32 KB
#define STG_BYTES (A_BYTES + B_BYTES)      // 48 KB
#define SM_TOTAL (4 * STG_BYTES)           // 192 KB

__device__ __forceinline__ void cp16(uint32_t dst, const void* src) {
    asm volatile("cp.async.cg.shared.global [%0], [%1], 16;" :: "r"(dst), "l"(src));
}
__device__ __forceinline__ void ldm_x4(uint32_t& r0, uint32_t& r1, uint32_t& r2, uint32_t& r3, uint32_t addr) {
    asm volatile("ldmatrix.sync.aligned.m8n8.x4.shared.b16 {%0,%1,%2,%3}, [%4];"
                 : "=r"(r0), "=r"(r1), "=r"(r2), "=r"(r3) : "r"(addr));
}
__device__ __forceinline__ void mma16816(float* d, const uint32_t* a, const uint32_t* b) {
    asm volatile("mma.sync.aligned.m16n8k16.row.col.f32.f16.f16.f32 "
                 "{%0,%1,%2,%3}, {%4,%5,%6,%7}, {%8,%9}, {%0,%1,%2,%3};"
                 : "+f"(d[0]), "+f"(d[1]), "+f"(d[2]), "+f"(d[3])
                 : "r"(a[0]), "r"(a[1]), "r"(a[2]), "r"(a[3]), "r"(b[0]), "r"(b[1]));
}

// Smem tile layout: row r x 128 bytes; physical = r*128 + (c16*16 ^ ((r&7)<<4))
__device__ __forceinline__ void load_stage(uint32_t sb, int stage,
                                           const __half* Ag, const __half* Bg,
                                           int chunk, int tid) {
    uint32_t sA = sb + stage * STG_BYTES;
    uint32_t sB = sA + A_BYTES;
    const char* gA = (const char*)Ag + (size_t)chunk * (BK * 2);
    const char* gB = (const char*)Bg + (size_t)chunk * (BK * 2);
#pragma unroll
    for (int j = 0; j < (A_BYTES / 16) / NTHR; j++) {   // 4 iters
        int seg = tid + j * NTHR;                       // row = seg>>3, c16 = seg&7
        uint32_t row = (uint32_t)seg >> 3;
        uint32_t off = row * 128u + ((((uint32_t)seg & 7u) * 16u) ^ ((row & 7u) << 4));
        cp16(sA + off, gA + (size_t)row * (KDIM * 2) + (size_t)((seg & 7) << 4));
    }
#pragma unroll
    for (int j = 0; j < (B_BYTES / 16) / NTHR; j++) {   // 8 iters
        int seg = tid + j * NTHR;
        uint32_t row = (uint32_t)seg >> 3;
        uint32_t off = row * 128u + ((((uint32_t)seg & 7u) * 16u) ^ ((row & 7u) << 4));
        cp16(sB + off, gB + (size_t)row * (KDIM * 2) + (size_t)((seg & 7) << 4));
    }
}

__global__ void __launch_bounds__(NTHR, 1)
k_gemm(float* __restrict__ y) {
    extern __shared__ char smem[];
    uint32_t sb = smem_u32(smem);
    int tid = threadIdx.x;
    int wid = tid >> 5, lid = tid & 31;
    int tn = blockIdx.x, tm = blockIdx.y;
    const __half* Ag = g_basis + (size_t)tm * BM * KDIM;
    const __half* Bg = g_coef + (size_t)tn * BN * KDIM;

    int wm = wid >> 2;          // 0..1 -> warp rows wm*64
    int wn = wid & 3;           // 0..3 -> warp cols wn*64

    // A fragments: mt 0..3 (m16 each)
    uint32_t aRow[4], aXor[4];
#pragma unroll
    for (int mt = 0; mt < 4; mt++) {
        aRow[mt] = (uint32_t)(wm * 64 + mt * 16 + (lid & 15));
        aXor[mt] = (aRow[mt] & 7u) << 4;
    }
    uint32_t aCol = (uint32_t)((lid >> 4) * 16);

    // B fragments: p 0..3 (n16 each -> two n8 tiles)
    uint32_t bRow[4], bXor[4];
#pragma unroll
    for (int p = 0; p < 4; p++) {
        bRow[p] = (uint32_t)(wn * 64 + p * 16 + ((lid >> 4) << 3) + (lid & 7));
        bXor[p] = (bRow[p] & 7u) << 4;
    }
    uint32_t bCol = (uint32_t)(((lid >> 3) & 1) * 16);

    float acc[4][8][4];
#pragma unroll
    for (int mt = 0; mt < 4; mt++)
#pragma unroll
        for (int nt = 0; nt < 8; nt++)
#pragma unroll
            for (int q = 0; q < 4; q++) acc[mt][nt][q] = 0.0f;

    // Prologue: chunks 0..3 into stages 0..3, one group.
#pragma unroll
    for (int s = 0; s < 4; s++) load_stage(sb, s, Ag, Bg, s, tid);
    asm volatile("cp.async.commit_group;" ::: "memory");

    uint32_t afr[2][4][4];   // [buf][mt][4]
    uint32_t bfr[2][4][4];   // [buf][p][4]

#pragma unroll 1
    for (int j = 0; j < NPAIR; j++) {
        // Pair j covers chunks 2j, 2j+1 in stage-pair {2*(j&1), 2*(j&1)+1}.
        asm volatile("cp.async.wait_group 0;" ::: "memory");
        __syncthreads();

        uint32_t bA0 = sb + (uint32_t)(2 * (j & 1)) * STG_BYTES;
        uint32_t bA1 = bA0 + STG_BYTES;

        // kk=0 fragments of first chunk into buf 0
#pragma unroll
        for (int mt = 0; mt < 4; mt++)
            ldm_x4(afr[0][mt][0], afr[0][mt][1], afr[0][mt][2], afr[0][mt][3],
                   bA0 + aRow[mt] * 128u + (aCol ^ aXor[mt]));
#pragma unroll
        for (int p = 0; p < 4; p++)
            ldm_x4(bfr[0][p][0], bfr[0][p][1], bfr[0][p][2], bfr[0][p][3],
                   bA0 + A_BYTES + bRow[p] * 128u + (bCol ^ bXor[p]));

        // Refill the stage-pair read during pair j-1 with chunks 2j+2, 2j+3
        // (safe: separated from those reads by the barrier above).
        if (j >= 1 && j < NPAIR - 1) {
            int nc = 2 * j + 2;
            load_stage(sb, nc & 3, Ag, Bg, nc, tid);
            load_stage(sb, (nc + 1) & 3, Ag, Bg, nc + 1, tid);
            asm volatile("cp.async.commit_group;" ::: "memory");
        }

        // 8 uninterrupted k-steps across both chunks of the pair.
#pragma unroll
        for (int kks = 0; kks < 8; kks++) {
            int cur = kks & 1, nxt = cur ^ 1;
            if (kks < 7) {
                int ns = kks + 1;
                uint32_t base = (ns < 4) ? bA0 : bA1;
                uint32_t koff = (uint32_t)(ns & 3) * 32u;
#pragma unroll
                for (int mt = 0; mt < 4; mt++)
                    ldm_x4(afr[nxt][mt][0], afr[nxt][mt][1], afr[nxt][mt][2], afr[nxt][mt][3],
                           base + aRow[mt] * 128u + ((koff + aCol) ^ aXor[mt]));
#pragma unroll
                for (int p = 0; p < 4; p++)
                    ldm_x4(bfr[nxt][p][0], bfr[nxt][p][1], bfr[nxt][p][2], bfr[nxt][p][3],
                           base + A_BYTES + bRow[p] * 128u + ((koff + bCol) ^ bXor[p]));
            }
#pragma unroll
            for (int mt = 0; mt < 4; mt++)
#pragma unroll
                for (int p = 0; p < 4; p++) {
                    mma16816(acc[mt][2 * p + 0], afr[cur][mt], &bfr[cur][p][0]);
                    mma16816(acc[mt][2 * p + 1], afr[cur][mt], &bfr[cur][p][2]);
                }
        }
    }

    // Epilogue: direct float2 stores
    int r0 = wm * 64 + (lid >> 2);
    int cb = wn * 64 + (lid & 3) * 2;
#pragma unroll
    for (int mt = 0; mt < 4; mt++) {
#pragma unroll
        for (int nt = 0; nt < 8; nt++) {
            int row = tm * BM + r0 + mt * 16;
            int col = tn * BN + cb + nt * 8;
            float2 v0 = make_float2(acc[mt][nt][0], acc[mt][nt][1]);
            float2 v1 = make_float2(acc[mt][nt][2], acc[mt][nt][3]);
            *reinterpret_cast<float2*>(y + (size_t)row * OUT_C + col) = v0;
            *reinterpret_cast<float2*>(y + (size_t)(row + 8) * OUT_C + col) = v1;
        }
    }
}

// ---------------------------------------------------------------------------
extern "C" void kernel_launch(void* const* d_in, const int* in_sizes, int n_in,
                              void* d_out, int out_size) {
    (void)in_sizes; (void)n_in; (void)out_size;
    const float* x       = (const float*)d_in[0];
    const float* coeffs  = (const float*)d_in[1];
    const float* centers = (const float*)d_in[2];
    const float* slopes  = (const float*)d_in[3];
    const float* alpha   = (const float*)d_in[4];
    const float* beta    = (const float*)d_in[5];
    float* y = (float*)d_out;

    k_pre<<<NB_BASIS + NB_CONV, 256>>>(x, coeffs, centers, slopes, alpha, beta);
    cudaFuncSetAttribute(k_gemm, cudaFuncAttributeMaxDynamicSharedMemorySize, SM_TOTAL);
    k_gemm<<<dim3(OUT_C / BN, BATCH / BM), NTHR, SM_TOTAL>>>(y);
}